// round 13
// baseline (speedup 1.0000x reference)
#include <cuda_runtime.h>
#include <math.h>

#define TSEQ 500
#define BATCH 512

typedef unsigned long long u64;

__device__ __forceinline__ void ffma2(u64& d, u64 a, u64 b, u64 c) {
    asm("fma.rn.f32x2 %0, %1, %2, %3;" : "=l"(d) : "l"(a), "l"(b), "l"(c));
}
__device__ __forceinline__ u64 fmul2(u64 a, u64 b) {
    u64 d; asm("mul.rn.f32x2 %0, %1, %2;" : "=l"(d) : "l"(a), "l"(b)); return d;
}
__device__ __forceinline__ float2 up2(u64 v) {
    float2 f; asm("mov.b64 {%0,%1}, %2;" : "=f"(f.x), "=f"(f.y) : "l"(v)); return f;
}
__device__ __forceinline__ u64 pk2(float x, float y) {
    u64 v; asm("mov.b64 %0, {%1,%2};" : "=l"(v) : "f"(x), "f"(y)); return v;
}
__device__ __forceinline__ void barh(int half) {
    asm volatile("bar.sync %0, 64;" :: "r"(half + 1) : "memory");
}

// CTA = 128 threads = 2 INDEPENDENT 64-thread batch-halves (named barriers).
// ht = tid&63, rg = ht>>3 (8 rows each), cg = ht&7 (8 cols each).
// Thread owns P[8rg..][8cg..] as P2[8][4] packed f32x2.
// K=4 blocked updates, ONE named barrier per block; 18 barriers/step.
// y/u double-buffered by step parity + register prefetch.

__global__ void __launch_bounds__(128, 2)
akf_main(const float* __restrict__ ext, const float* __restrict__ obs,
         const float* __restrict__ mu0, const float* __restrict__ sg0,
         const float* __restrict__ lsig, const float* __restrict__ Bm,
         const float* __restrict__ Hm, const float* __restrict__ ldel,
         float* __restrict__ out)
{
    __shared__ __align__(16) float sh_H[4096];
    __shared__ __align__(16) float sh_B[2048];
    __shared__ __align__(16) float sh_V[2][2][4][64];   // [half][pb][j][row]
    __shared__ __align__(16) float sh_GP[2][2][16][2];  // [half][pb][entry][warp]
    __shared__ __align__(16) float sh_mu[2][64];
    __shared__ __align__(16) float sh_y[2][2][64];      // [half][t&1][..]
    __shared__ __align__(16) float sh_u[2][2][32];
    __shared__ float sh_r[64], sh_q[64];

    const int tid  = threadIdx.x;
    const int half = tid >> 6;
    const int ht   = tid & 63;
    const int b    = (blockIdx.x << 1) | half;
    const int rg   = ht >> 3;
    const int cg   = ht & 7;
    const int r0   = rg << 3;
    const int c0   = cg << 3;
    const int lane = tid & 31;
    const int wh   = (ht >> 5) & 1;
    const bool zon = (lane < 8);
    const bool diag = (rg == cg);
    const bool bb2 = cg & 4, bb1 = cg & 2, bb0 = cg & 1;

    for (int i = tid; i < 4096; i += 128) sh_H[i] = Hm[i];
    for (int i = tid; i < 2048; i += 128) sh_B[i] = Bm[i];
    if (tid < 64) {
        float e = expf(ldel[tid]); sh_r[tid] = e * e;
        float f = expf(lsig[tid]); sh_q[tid] = f * f;
    }

    u64 P2[8][4];
    #pragma unroll
    for (int a = 0; a < 8; ++a)
        #pragma unroll
        for (int k = 0; k < 4; ++k) P2[a][k] = 0ull;

    float* outmu = out;
    float* outls = out + (size_t)TSEQ * BATCH * 64;

    {
        float m0  = mu0[b * 64 + ht];
        float s0v = sg0[b * 64 + ht];
        sh_mu[half][ht] = m0;
        outmu[b * 64 + ht] = m0;
        outls[b * 64 + ht] = logf(s0v);
    }
    if (diag) {
        #pragma unroll
        for (int a = 0; a < 8; ++a) {
            float s0v = sg0[b * 64 + r0 + a];
            float2 e = up2(P2[a][a >> 1]);
            if (a & 1) e.y = s0v * s0v; else e.x = s0v * s0v;
            P2[a][a >> 1] = pk2(e.x, e.y);
        }
    }
    // y/u for t=1 (parity 1)
    sh_y[half][1][ht] = obs[((size_t)1 * BATCH + b) * 64 + ht];
    if (ht < 32) sh_u[half][1][ht] = ext[((size_t)0 * BATCH + b) * 32 + ht];
    __syncthreads();

    for (int t = 1; t < TSEQ; ++t) {
        const int tb = t & 1;

        // ---- predict: mu += B u ; P += diag(q) ----
        {
            float s = sh_mu[half][ht];
            const float* Br = &sh_B[ht * 32];
            #pragma unroll 8
            for (int k = 0; k < 32; ++k) s += Br[k] * sh_u[half][tb][k];
            sh_mu[half][ht] = s;
        }
        if (diag) {
            #pragma unroll
            for (int a = 0; a < 8; ++a) {
                float qv = sh_q[r0 + a];
                float2 e = up2(P2[a][a >> 1]);
                if (a & 1) e.y += qv; else e.x += qv;
                P2[a][a >> 1] = pk2(e.x, e.y);
            }
        }
        barh(half);

        // mu col strip -> registers (replicated)
        u64 mc2[4];
        {
            const ulonglong2* mp = (const ulonglong2*)&sh_mu[half][c0];
            ulonglong2 ma = mp[0], mb = mp[1];
            mc2[0] = ma.x; mc2[1] = ma.y; mc2[2] = mb.x; mc2[3] = mb.y;
        }

        // prefetch y/u for t+1 (clamped; latency hidden under the blocks)
        const int tn = (t + 1 < TSEQ) ? t + 1 : t;
        float ry = obs[((size_t)tn * BATCH + b) * 64 + ht];
        float ru = 0.0f;
        if (ht < 32) ru = ext[((size_t)(tn - 1) * BATCH + b) * 32 + ht];

        // ---- 16 blocks of 4 observations, one named barrier each ----
        #pragma unroll 1
        for (int blk = 0; blk < 16; ++blk) {
            const int o  = blk << 2;
            const int pb = blk & 1;
            float* V = &sh_V[half][pb][0][0];

            // phase 1a: vp partials, V rows, z partials
            float vp[4][8];
            float zz[4];
            #pragma unroll
            for (int j = 0; j < 4; ++j) {
                const ulonglong2* hp = (const ulonglong2*)&sh_H[((o + j) << 6) + c0];
                ulonglong2 ha = hp[0], hb = hp[1];
                u64 h2[4] = {ha.x, ha.y, hb.x, hb.y};
                #pragma unroll
                for (int a = 0; a < 8; ++a) {
                    u64 acc = 0ull;
                    ffma2(acc, P2[a][0], h2[0], acc);
                    ffma2(acc, P2[a][1], h2[1], acc);
                    ffma2(acc, P2[a][2], h2[2], acc);
                    ffma2(acc, P2[a][3], h2[3], acc);
                    float2 f = up2(acc);
                    vp[j][a] = f.x + f.y;
                }
                float k4[4], k2[2];
                #pragma unroll
                for (int m = 0; m < 4; ++m) {
                    float keep = bb2 ? vp[j][m + 4] : vp[j][m];
                    float send = bb2 ? vp[j][m]     : vp[j][m + 4];
                    k4[m] = keep + __shfl_xor_sync(0xffffffffu, send, 4);
                }
                #pragma unroll
                for (int m = 0; m < 2; ++m) {
                    float keep = bb1 ? k4[m + 2] : k4[m];
                    float send = bb1 ? k4[m]     : k4[m + 2];
                    k2[m] = keep + __shfl_xor_sync(0xffffffffu, send, 2);
                }
                float keep = bb0 ? k2[1] : k2[0];
                float send = bb0 ? k2[0] : k2[1];
                float kk = keep + __shfl_xor_sync(0xffffffffu, send, 1);
                V[(j << 6) + ht] = kk;
                u64 za = 0ull;
                ffma2(za, h2[0], mc2[0], za);
                ffma2(za, h2[1], mc2[1], za);
                ffma2(za, h2[2], mc2[2], za);
                ffma2(za, h2[3], mc2[3], za);
                float2 zf = up2(za);
                zz[j] = zon ? (zf.x + zf.y) : 0.0f;
            }

            // phase 1b: PACKED Gram partials + 16-value butterfly reduce-scatter
            {
                u64 vpp[4][4];
                #pragma unroll
                for (int k = 0; k < 4; ++k)
                    #pragma unroll
                    for (int m = 0; m < 4; ++m)
                        vpp[k][m] = pk2(vp[k][2 * m], vp[k][2 * m + 1]);
                u64 hq2[4][4];
                #pragma unroll
                for (int j = 0; j < 4; ++j) {
                    const ulonglong2* hr = (const ulonglong2*)&sh_H[((o + j) << 6) + r0];
                    ulonglong2 ha = hr[0], hb = hr[1];
                    hq2[j][0] = ha.x; hq2[j][1] = ha.y; hq2[j][2] = hb.x; hq2[j][3] = hb.y;
                }
                #define GD(j, k) ({ u64 acc = 0ull; \
                    ffma2(acc, hq2[j][0], vpp[k][0], acc); \
                    ffma2(acc, hq2[j][1], vpp[k][1], acc); \
                    ffma2(acc, hq2[j][2], vpp[k][2], acc); \
                    ffma2(acc, hq2[j][3], vpp[k][3], acc); \
                    float2 f = up2(acc); f.x + f.y; })
                float val[16];
                val[0] = GD(0, 0); val[1] = GD(1, 0); val[2] = GD(1, 1);
                val[3] = GD(2, 0); val[4] = GD(2, 1); val[5] = GD(2, 2);
                val[6] = GD(3, 0); val[7] = GD(3, 1); val[8] = GD(3, 2);
                val[9] = GD(3, 3);
                #undef GD
                val[10] = zz[0]; val[11] = zz[1]; val[12] = zz[2]; val[13] = zz[3];
                val[14] = 0.0f;  val[15] = 0.0f;

                const bool b3 = lane & 8, b2l = lane & 4, b1 = lane & 2, b0 = lane & 1;
                #pragma unroll
                for (int k = 0; k < 8; ++k) {
                    float keep = b3 ? val[k + 8] : val[k];
                    float send = b3 ? val[k]     : val[k + 8];
                    val[k] = keep + __shfl_xor_sync(0xffffffffu, send, 8);
                }
                #pragma unroll
                for (int k = 0; k < 4; ++k) {
                    float keep = b2l ? val[k + 4] : val[k];
                    float send = b2l ? val[k]     : val[k + 4];
                    val[k] = keep + __shfl_xor_sync(0xffffffffu, send, 4);
                }
                #pragma unroll
                for (int k = 0; k < 2; ++k) {
                    float keep = b1 ? val[k + 2] : val[k];
                    float send = b1 ? val[k]     : val[k + 2];
                    val[k] = keep + __shfl_xor_sync(0xffffffffu, send, 2);
                }
                {
                    float keep = b0 ? val[1] : val[0];
                    float send = b0 ? val[0] : val[1];
                    val[0] = keep + __shfl_xor_sync(0xffffffffu, send, 1);
                }
                val[0] += __shfl_xor_sync(0xffffffffu, val[0], 16);
                if (lane < 14) sh_GP[half][pb][lane][wh] = val[0];
            }
            barh(half);   // the ONLY barrier per block

            // phase 3: merge warp partials (paired LDS.128), K-space recursion
            float g00, u01, g11, u02, g21, g22, u03, g31, g32, g33, z0, z1, z2, z3;
            #define GPAIR(e, A, B) { float4 q = *(const float4*)&sh_GP[half][pb][e][0]; \
                                     A = q.x + q.y; B = q.z + q.w; }
            GPAIR(0,  g00, u01) GPAIR(2,  g11, u02) GPAIR(4,  g21, g22)
            GPAIR(6,  u03, g31) GPAIR(8,  g32, g33)
            GPAIR(10, z0,  z1 ) GPAIR(12, z2,  z3 )
            #undef GPAIR
            z0 *= 0.5f; z1 *= 0.5f; z2 *= 0.5f; z3 *= 0.5f;

            float rs0 = __fdividef(1.0f, g00 + sh_r[o + 0]);
            float c01 = u01 * rs0, c02 = u02 * rs0, c03 = u03 * rs0;
            float u12 = g21 - c01 * u02;
            float u13 = g31 - c01 * u03;
            float rs1 = __fdividef(1.0f, (g11 - c01 * u01) + sh_r[o + 1]);
            float c12 = u12 * rs1, c13 = u13 * rs1;
            float u23 = g32 - c02 * u03 - c12 * u13;
            float rs2 = __fdividef(1.0f, (g22 - c02 * u02 - c12 * u12) + sh_r[o + 2]);
            float c23 = u23 * rs2;
            float rs3 = __fdividef(1.0f, (g33 - c03 * u03 - c13 * u13 - c23 * u23) + sh_r[o + 3]);
            float f0 = (sh_y[half][tb][o + 0] - z0) * rs0;
            float f1 = (sh_y[half][tb][o + 1] - z1 - u01 * f0) * rs1;
            float f2 = (sh_y[half][tb][o + 2] - z2 - u02 * f0 - u12 * f1) * rs2;
            float f3 = (sh_y[half][tb][o + 3] - z3 - u03 * f0 - u13 * f1 - u23 * f2) * rs3;

            // phase 4: w col strips, mu update, pre-scaled rank-4
            u64 wc[4][4];
            {
                const ulonglong2* q0 = (const ulonglong2*)&V[0 * 64 + c0];
                const ulonglong2* q1 = (const ulonglong2*)&V[1 * 64 + c0];
                const ulonglong2* q2 = (const ulonglong2*)&V[2 * 64 + c0];
                const ulonglong2* q3 = (const ulonglong2*)&V[3 * 64 + c0];
                ulonglong2 a0 = q0[0], e0 = q0[1];
                wc[0][0] = a0.x; wc[0][1] = a0.y; wc[0][2] = e0.x; wc[0][3] = e0.y;
                ulonglong2 a1 = q1[0], e1 = q1[1];
                wc[1][0] = a1.x; wc[1][1] = a1.y; wc[1][2] = e1.x; wc[1][3] = e1.y;
                ulonglong2 a2 = q2[0], e2 = q2[1];
                wc[2][0] = a2.x; wc[2][1] = a2.y; wc[2][2] = e2.x; wc[2][3] = e2.y;
                ulonglong2 a3 = q3[0], e3 = q3[1];
                wc[3][0] = a3.x; wc[3][1] = a3.y; wc[3][2] = e3.x; wc[3][3] = e3.y;
                u64 n01 = pk2(-c01, -c01), n02 = pk2(-c02, -c02), n03 = pk2(-c03, -c03);
                u64 n12 = pk2(-c12, -c12), n13 = pk2(-c13, -c13), n23 = pk2(-c23, -c23);
                #pragma unroll
                for (int k = 0; k < 4; ++k) {
                    ffma2(wc[1][k], n01, wc[0][k], wc[1][k]);
                    ffma2(wc[2][k], n02, wc[0][k], wc[2][k]);
                    ffma2(wc[2][k], n12, wc[1][k], wc[2][k]);
                    ffma2(wc[3][k], n03, wc[0][k], wc[3][k]);
                    ffma2(wc[3][k], n13, wc[1][k], wc[3][k]);
                    ffma2(wc[3][k], n23, wc[2][k], wc[3][k]);
                }
            }
            {
                u64 f02 = pk2(f0, f0), f12 = pk2(f1, f1);
                u64 f22 = pk2(f2, f2), f32 = pk2(f3, f3);
                #pragma unroll
                for (int k = 0; k < 4; ++k) {
                    ffma2(mc2[k], f02, wc[0][k], mc2[k]);
                    ffma2(mc2[k], f12, wc[1][k], mc2[k]);
                    ffma2(mc2[k], f22, wc[2][k], mc2[k]);
                    ffma2(mc2[k], f32, wc[3][k], mc2[k]);
                }
            }
            {
                u64 m0s = pk2(-rs0, -rs0), m1s = pk2(-rs1, -rs1);
                u64 m2s = pk2(-rs2, -rs2), m3s = pk2(-rs3, -rs3);
                #pragma unroll
                for (int k = 0; k < 4; ++k) {
                    wc[0][k] = fmul2(wc[0][k], m0s);
                    wc[1][k] = fmul2(wc[1][k], m1s);
                    wc[2][k] = fmul2(wc[2][k], m2s);
                    wc[3][k] = fmul2(wc[3][k], m3s);
                }
            }
            float wr[4][8];
            #pragma unroll
            for (int j = 0; j < 4; ++j) {
                float4 pa = *(const float4*)&V[(j << 6) + r0];
                float4 pe = *(const float4*)&V[(j << 6) + r0 + 4];
                wr[j][0] = pa.x; wr[j][1] = pa.y; wr[j][2] = pa.z; wr[j][3] = pa.w;
                wr[j][4] = pe.x; wr[j][5] = pe.y; wr[j][6] = pe.z; wr[j][7] = pe.w;
            }
            #pragma unroll
            for (int a = 0; a < 8; ++a) {
                wr[1][a] -= c01 * wr[0][a];
                wr[2][a] -= c02 * wr[0][a] + c12 * wr[1][a];
                wr[3][a] -= c03 * wr[0][a] + c13 * wr[1][a] + c23 * wr[2][a];
            }
            #pragma unroll
            for (int i = 0; i < 4; ++i) {
                #pragma unroll
                for (int a = 0; a < 8; ++a) {
                    u64 g = pk2(wr[i][a], wr[i][a]);
                    ffma2(P2[a][0], g, wc[i][0], P2[a][0]);
                    ffma2(P2[a][1], g, wc[i][1], P2[a][1]);
                    ffma2(P2[a][2], g, wc[i][2], P2[a][2]);
                    ffma2(P2[a][3], g, wc[i][3], P2[a][3]);
                }
            }
        }

        // ---- outputs ; publish mu ; stage next step's y/u ----
        if (ht < 8) {
            float2 m0f = up2(mc2[0]), m1f = up2(mc2[1]);
            float2 m2f = up2(mc2[2]), m3f = up2(mc2[3]);
            float4 lo = make_float4(m0f.x, m0f.y, m1f.x, m1f.y);
            float4 hi = make_float4(m2f.x, m2f.y, m3f.x, m3f.y);
            float* op = &outmu[((size_t)t * BATCH + b) * 64 + c0];
            *(float4*)op = lo;
            *(float4*)(op + 4) = hi;
            *(float4*)&sh_mu[half][c0] = lo;
            *(float4*)&sh_mu[half][c0 + 4] = hi;
        }
        if (diag) {
            #pragma unroll
            for (int a = 0; a < 8; ++a) {
                float2 e = up2(P2[a][a >> 1]);
                float dv = (a & 1) ? e.y : e.x;
                outls[((size_t)t * BATCH + b) * 64 + r0 + a] = 0.5f * logf(dv);
            }
        }
        sh_y[half][tb ^ 1][ht] = ry;
        if (ht < 32) sh_u[half][tb ^ 1][ht] = ru;
        barh(half);
    }
}

extern "C" void kernel_launch(void* const* d_in, const int* in_sizes, int n_in,
                              void* d_out, int out_size) {
    const float* ext  = (const float*)d_in[0];   // (500, 512, 32)
    const float* obs  = (const float*)d_in[1];   // (500, 512, 64)
    const float* mu0  = (const float*)d_in[2];   // (512, 64)
    const float* sg0  = (const float*)d_in[3];   // (512, 64)
    const float* lsig = (const float*)d_in[4];   // (64,)
    const float* Bm   = (const float*)d_in[5];   // (64, 32)
    const float* H    = (const float*)d_in[6];   // (64, 64)
    const float* ldel = (const float*)d_in[7];   // (64,)
    float* out = (float*)d_out;

    akf_main<<<BATCH / 2, 128>>>(ext, obs, mu0, sg0, lsig, Bm, H, ldel, out);
}